// round 5
// baseline (speedup 1.0000x reference)
#include <cuda_runtime.h>

#define FH 50
#define FW 50
#define CH 256
#define BATCH 4
#define NROI 1024
#define HOUT 7
#define WOUT 7
#define NBIN (HOUT*WOUT)
#define RATIO (1.0f/32.0f)
#define NGRP 4
#define TPB (128*NGRP)

typedef unsigned long long ull;

// smem: tile[CH*NBIN]f32 + offA..D int4[NBIN] + 4x packed-weight ulonglong2[NBIN] + flag int[NBIN]
#define SMEM_BYTES (CH*NBIN*4 + 4*NBIN*16 + 4*NBIN*16 + NBIN*4)

// Features transposed to BHWC so channel reads are contiguous.
__device__ float g_feats[BATCH * FH * FW * CH];

// ---------------------------------------------------------------------------
// packed f32x2 helpers (FFMA2/FMUL2 in SASS — only reachable via PTX)
// ---------------------------------------------------------------------------
__device__ __forceinline__ ull pk2(float x, float y) {
    ull r; asm("mov.b64 %0, {%1,%2};" : "=l"(r) : "f"(x), "f"(y)); return r;
}
__device__ __forceinline__ ull mul2(ull a, ull b) {
    ull r; asm("mul.rn.f32x2 %0, %1, %2;" : "=l"(r) : "l"(a), "l"(b)); return r;
}
__device__ __forceinline__ ull fma2(ull a, ull b, ull c) {
    ull r; asm("fma.rn.f32x2 %0, %1, %2, %3;" : "=l"(r) : "l"(a), "l"(b), "l"(c)); return r;
}
__device__ __forceinline__ float2 up2(ull a) {
    float2 v; asm("mov.b64 {%0,%1}, %2;" : "=f"(v.x), "=f"(v.y) : "l"(a)); return v;
}

// bilinear (packed, 2 channels) + scalar max
#define PSAMPLE(m0, m1, q00, q01, q10, q11, xh2, xl2, yb2, yt2)     \
    do {                                                            \
        ull _t = fma2(xh2, q01, mul2(xl2, q00));                    \
        ull _b = fma2(xh2, q11, mul2(xl2, q10));                    \
        float2 _v = up2(fma2(yb2, _b, mul2(yt2, _t)));              \
        m0 = fmaxf(m0, _v.x);                                       \
        m1 = fmaxf(m1, _v.y);                                       \
    } while (0)

// ---------------------------------------------------------------------------
// Kernel 1: BCHW -> BHWC transpose. One block per (b, h) row.
// ---------------------------------------------------------------------------
__global__ void transpose_feats_kernel(const float* __restrict__ in) {
    __shared__ float tile[CH * FW];   // tile[c*FW + w]
    int b = blockIdx.x / FH;
    int h = blockIdx.x % FH;
    const float* src = in + (size_t)b * CH * FH * FW + (size_t)h * FW;
    for (int idx = threadIdx.x; idx < CH * FW; idx += blockDim.x) {
        int c = idx / FW, w = idx % FW;
        tile[idx] = src[(size_t)c * FH * FW + w];
    }
    __syncthreads();
    float* dst = g_feats + (size_t)(b * FH + h) * FW * CH;  // dst[w*CH + c]
    for (int idx = threadIdx.x; idx < FW * CH; idx += blockDim.x) {
        int w = idx / CH, c = idx % CH;
        dst[idx] = tile[c * FW + w];
    }
}

// ---------------------------------------------------------------------------
// Kernel 2: RoIAlign. One block per roi, 512 threads.
//   Phase A (threads 0..48): per-bin geometry -> combined corner offsets
//     (row+col pre-summed, float2 units) for corner sets A/B/C/D, packed
//     duplicated weights, same-cell flags. Invalid bins get zeroed y-weights.
//   Phase B: tid&127 = channel pair, tid>>7 = bin group. Packed f32x2
//     bilinear; corner sets deduped via warp-uniform flags.
//   Phase C: coalesced float4 flush of the staged (C,49) tile.
// ---------------------------------------------------------------------------
__global__ __launch_bounds__(TPB, 2)
void roialign_kernel(const float* __restrict__ rois,
                     float* __restrict__ out) {
    extern __shared__ float smem[];
    float*      tile   = smem;                                // [CH][NBIN]
    int4*       g_offA = (int4*)(smem + CH * NBIN);           // [NBIN]
    int4*       g_offB = g_offA + NBIN;
    int4*       g_offC = g_offB + NBIN;
    int4*       g_offD = g_offC + NBIN;
    ulonglong2* g_wx0  = (ulonglong2*)(g_offD + NBIN);        // {xh0_2, xl0_2}
    ulonglong2* g_wx1  = g_wx0 + NBIN;                        // {xh1_2, xl1_2}
    ulonglong2* g_wy0  = g_wx1 + NBIN;                        // {yb0_2, yt0_2}
    ulonglong2* g_wy1  = g_wy0 + NBIN;                        // {yb1_2, yt1_2}
    int*        g_flag = (int*)(g_wy1 + NBIN);                // bit0 sameX, bit1 sameY

    int r   = blockIdx.x;
    int tid = threadIdx.x;

    int b = (int)__ldg(&rois[r * 5 + 0]);
    const ull* fbase = (const ull*)g_feats + (size_t)b * FH * FW * (CH / 2);

    // ---- Phase A ----
    if (tid < NBIN) {
        float bx1 = fminf(fmaxf(__ldg(&rois[r * 5 + 1]) * RATIO, 0.f), (float)FW);
        float by1 = fminf(fmaxf(__ldg(&rois[r * 5 + 2]) * RATIO, 0.f), (float)FH);
        float bx2 = fminf(fmaxf(__ldg(&rois[r * 5 + 3]) * RATIO, 0.f), (float)FW);
        float by2 = fminf(fmaxf(__ldg(&rois[r * 5 + 4]) * RATIO, 0.f), (float)FH);
        bool roi_valid = (bx2 - bx1 > 0.f) && (by2 - by1 > 0.f);
        float bin_w = (bx2 - bx1) * (1.0f / WOUT);
        float bin_h = (by2 - by1) * (1.0f / HOUT);

        int i = tid / WOUT;
        int j = tid - i * WOUT;

        float y1u = by1 + (float)i * bin_h;
        float y1b = fminf(fmaxf(y1u, 0.f), (float)FH);
        float y2b = fminf(fmaxf(y1u + bin_h, 0.f), (float)FH);
        float x1u = bx1 + (float)j * bin_w;
        float x1b = fminf(fmaxf(x1u, 0.f), (float)FW);
        float x2b = fminf(fmaxf(x1u + bin_w, 0.f), (float)FW);
        bool valid = roi_valid && (x2b > x1b) && (y2b > y1b);
        float vscale = valid ? 1.f : 0.f;

        int   rowi[4], coli[4];
        float wyv[4], wxv[4];
#pragma unroll
        for (int t = 0; t < 2; t++) {
            float py = y1b + ((float)t + 0.5f) * (bin_h * 0.5f);
            float yl = fminf(fmaxf(floorf(py), 0.f), (float)(FH - 1));
            int ylI = (int)yl;
            int yhI = min(ylI + 1, FH - 1);
            rowi[2 * t + 0] = ylI * FW * (CH / 2);
            rowi[2 * t + 1] = yhI * FW * (CH / 2);
            wyv[2 * t + 0] = (py - yl) * vscale;          // wyb (zeroed if invalid)
            wyv[2 * t + 1] = ((float)yhI - py) * vscale;  // wyt (NOT 1-wyb)

            float px = x1b + ((float)t + 0.5f) * (bin_w * 0.5f);
            float xl = fminf(fmaxf(floorf(px), 0.f), (float)(FW - 1));
            int xlI = (int)xl;
            int xhI = min(xlI + 1, FW - 1);
            coli[2 * t + 0] = xlI * (CH / 2);
            coli[2 * t + 1] = xhI * (CH / 2);
            wxv[2 * t + 0] = px - xl;          // wxh
            wxv[2 * t + 1] = (float)xhI - px;  // wxl
        }
        // combined offsets: rows pair {0,1} x cols pair {0,1} per corner set
        g_offA[tid] = make_int4(rowi[0] + coli[0], rowi[0] + coli[1],
                                rowi[1] + coli[0], rowi[1] + coli[1]);
        g_offB[tid] = make_int4(rowi[0] + coli[2], rowi[0] + coli[3],
                                rowi[1] + coli[2], rowi[1] + coli[3]);
        g_offC[tid] = make_int4(rowi[2] + coli[0], rowi[2] + coli[1],
                                rowi[3] + coli[0], rowi[3] + coli[1]);
        g_offD[tid] = make_int4(rowi[2] + coli[2], rowi[2] + coli[3],
                                rowi[3] + coli[2], rowi[3] + coli[3]);
        ulonglong2 w;
        w.x = pk2(wxv[0], wxv[0]); w.y = pk2(wxv[1], wxv[1]); g_wx0[tid] = w;
        w.x = pk2(wxv[2], wxv[2]); w.y = pk2(wxv[3], wxv[3]); g_wx1[tid] = w;
        w.x = pk2(wyv[0], wyv[0]); w.y = pk2(wyv[1], wyv[1]); g_wy0[tid] = w;
        w.x = pk2(wyv[2], wyv[2]); w.y = pk2(wyv[3], wyv[3]); g_wy1[tid] = w;
        int sameX = (coli[2] == coli[0]) && (coli[3] == coli[1]);
        int sameY = (rowi[2] == rowi[0]) && (rowi[3] == rowi[1]);
        g_flag[tid] = sameX | (sameY << 1);
    }
    __syncthreads();

    // ---- Phase B ----
    int c2  = tid & 127;       // channel pair 0..127
    int grp = tid >> 7;        // bin group 0..3
    const ull* fb2 = fbase + c2;

    for (int k = grp; k < NBIN; k += NGRP) {
        int4       oA  = g_offA[k];
        ulonglong2 wx0 = g_wx0[k];
        ulonglong2 wx1 = g_wx1[k];
        ulonglong2 wy0 = g_wy0[k];
        ulonglong2 wy1 = g_wy1[k];
        int fl = g_flag[k];
        bool sameX = fl & 1;
        bool sameY = fl & 2;

        // Corner set A (always)
        ull a00 = fb2[oA.x], a01 = fb2[oA.y], a10 = fb2[oA.z], a11 = fb2[oA.w];
        float m0 = -3.402823466e38f, m1 = -3.402823466e38f;
        PSAMPLE(m0, m1, a00, a01, a10, a11, wx0.x, wx0.y, wy0.x, wy0.y);

        // Corner set B: rows pair0 x cols pair1
        ull b00, b01, b10, b11;
        if (sameX) { b00 = a00; b01 = a01; b10 = a10; b11 = a11; }
        else {
            int4 oB = g_offB[k];
            b00 = fb2[oB.x]; b01 = fb2[oB.y]; b10 = fb2[oB.z]; b11 = fb2[oB.w];
        }
        PSAMPLE(m0, m1, b00, b01, b10, b11, wx1.x, wx1.y, wy0.x, wy0.y);

        // Corner sets C (rows pair1 x cols pair0), D (rows pair1 x cols pair1)
        ull c00, c01, c10, c11, d00, d01, d10, d11;
        if (sameY) {
            c00 = a00; c01 = a01; c10 = a10; c11 = a11;
            d00 = b00; d01 = b01; d10 = b10; d11 = b11;
        } else {
            int4 oC = g_offC[k];
            c00 = fb2[oC.x]; c01 = fb2[oC.y]; c10 = fb2[oC.z]; c11 = fb2[oC.w];
            if (sameX) { d00 = c00; d01 = c01; d10 = c10; d11 = c11; }
            else {
                int4 oD = g_offD[k];
                d00 = fb2[oD.x]; d01 = fb2[oD.y]; d10 = fb2[oD.z]; d11 = fb2[oD.w];
            }
        }
        PSAMPLE(m0, m1, c00, c01, c10, c11, wx0.x, wx0.y, wy1.x, wy1.y);
        PSAMPLE(m0, m1, d00, d01, d10, d11, wx1.x, wx1.y, wy1.x, wy1.y);

        tile[(2 * c2 + 0) * NBIN + k] = m0;
        tile[(2 * c2 + 1) * NBIN + k] = m1;
    }
    __syncthreads();

    // ---- Phase C: tile[c*49 + k] is exactly (N,C,7,7) order for this roi ----
    float4* dst4       = (float4*)(out + (size_t)r * CH * NBIN);
    const float4* src4 = (const float4*)tile;
    for (int idx = tid; idx < CH * NBIN / 4; idx += blockDim.x)
        dst4[idx] = src4[idx];
}

extern "C" void kernel_launch(void* const* d_in, const int* in_sizes, int n_in,
                              void* d_out, int out_size) {
    const float* feats = (const float*)d_in[0];   // (4,256,50,50) f32
    const float* rois  = (const float*)d_in[1];   // (1024,5) f32
    float* out = (float*)d_out;                   // (1024,256,7,7) f32

    cudaFuncSetAttribute(roialign_kernel,
                         cudaFuncAttributeMaxDynamicSharedMemorySize, SMEM_BYTES);

    transpose_feats_kernel<<<BATCH * FH, 512>>>(feats);
    roialign_kernel<<<NROI, TPB, SMEM_BYTES>>>(rois, out);
}